// round 17
// baseline (speedup 1.0000x reference)
#include <cuda_runtime.h>
#include <cuda_bf16.h>
#include <cstdint>

// Problem constants
#define BS     64
#define NSTK   64
#define NHALF  32
#define COORD  32
#define SPEMB  256
#define DNIN   128
#define DNOUT  256
#define NPNT   64
#define QOUT   32
#define KTOT   (DNIN*3)              // 384
#define NTOTPNT (NSTK*NPNT)          // 4096
#define YTOT   (BS*DNOUT*NHALF*QOUT) // 16777216

// GEMM: Y[256,65536] = W[256,384] x B[384,65536]
// K reordered as k = kk*128 + i. 6 physical chunks of 64 (kk = c>>1, i0 = (c&1)*64).
// Per chunk: 3 mma passes (Ah*Bh, Al*Bh, Ah*Bl) into shared accumulators.
// CTA tile M=128 x N=64 (grid = 1024 ntiles x 2 mt). smem 48KB -> 3 CTAs/SM.
#define NTILES 1024                  // (b, 2-stroke group): 64 n = 2 strokes x 32 q
#define NCHUNK 6
// smem: Ah 16K | Al 16K | Bh 8K | Bl 8K
#define SMEM_GEMM 49152

// Scratch (device globals; no allocation allowed)
__device__ int   g_idx[BS*NHALF];
// A blobs [12][2 mt][128 m][64 i] bf16: j<6 hi, j>=6 lo; per (j,mt) 16KB
__device__ __align__(16) __nv_bfloat16 g_Ab[12*2*128*64];    // 384 KB
__device__ float g_y[YTOT];
__device__ float g_ps[DNOUT*NTILES];
__device__ float g_pq[DNOUT*NTILES];
__device__ float g_mean[DNOUT];
__device__ float g_rstd[DNOUT];

// ---------------------------------------------------------------------------
// helpers
// ---------------------------------------------------------------------------
__device__ __forceinline__ uint32_t smem_u32(const void* p) {
    uint32_t a;
    asm("{ .reg .u64 t; cvta.to.shared.u64 t, %1; cvt.u32.u64 %0, t; }" : "=r"(a) : "l"(p));
    return a;
}
__device__ __forceinline__ void cp16(uint32_t dst, const void* src) {
    asm volatile("cp.async.cg.shared.global [%0], [%1], 16;\n" :: "r"(dst), "l"(src));
}
__device__ __forceinline__ void ldsm_x4(uint32_t addr, uint32_t* r) {
    asm volatile("ldmatrix.sync.aligned.m8n8.x4.shared.b16 {%0,%1,%2,%3}, [%4];"
        : "=r"(r[0]), "=r"(r[1]), "=r"(r[2]), "=r"(r[3]) : "r"(addr));
}
__device__ __forceinline__ void mma16816(float* d, const uint32_t* a, uint32_t b0, uint32_t b1) {
    asm volatile("mma.sync.aligned.m16n8k16.row.col.f32.bf16.bf16.f32 "
        "{%0,%1,%2,%3}, {%4,%5,%6,%7}, {%8,%9}, {%0,%1,%2,%3};"
        : "+f"(d[0]), "+f"(d[1]), "+f"(d[2]), "+f"(d[3])
        : "r"(a[0]), "r"(a[1]), "r"(a[2]), "r"(a[3]), "r"(b0), "r"(b1));
}
__device__ __forceinline__ uint32_t pack_bf16x2(float lo16, float hi16) {
    __nv_bfloat162 h = __floats2bfloat162_rn(lo16, hi16);   // x=lower addr, y=upper
    return *(uint32_t*)&h;
}

// ---------------------------------------------------------------------------
// 1) FPS. Parallel argmax via shfl (strict > keeps FIRST max: each lane's
//    aggregate covers lower indices than its shfl_down partner).
// ---------------------------------------------------------------------------
__global__ void fps_kernel(const float* __restrict__ coor) {
    int b = blockIdx.x;
    int j = threadIdx.x;           // 0..63
    __shared__ float sx[NSTK][COORD + 1];
    __shared__ int   far;
    __shared__ float wv[2];
    __shared__ int   wi2[2];

    const float* base = coor + (size_t)b * NSTK * COORD;
    #pragma unroll
    for (int c = 0; c < COORD; c++) sx[j][c] = base[j * COORD + c];
    float sdj = 1e10f;
    if (j == 0) far = 0;
    __syncthreads();

    for (int i = 0; i < NHALF; i++) {
        int f = far;
        if (j == 0) g_idx[b * NHALF + i] = f;
        float d = 0.f;
        #pragma unroll
        for (int c = 0; c < COORD; c++) {
            float t = sx[j][c] - sx[f][c];
            d += t * t;
        }
        sdj = fminf(sdj, d);
        float v = sdj; int bi = j;
        #pragma unroll
        for (int dd = 16; dd > 0; dd >>= 1) {
            float ov = __shfl_down_sync(0xffffffffu, v, dd);
            int   oi = __shfl_down_sync(0xffffffffu, bi, dd);
            if (ov > v) { v = ov; bi = oi; }    // strict: keep lower index
        }
        if ((j & 31) == 0) { wv[j >> 5] = v; wi2[j >> 5] = bi; }
        __syncthreads();
        if (j == 0) {
            float v0 = wv[0], v1 = wv[1];
            far = (v1 > v0) ? wi2[1] : wi2[0];
        }
        __syncthreads();
    }
}

// ---------------------------------------------------------------------------
// 2) merged gathers (sparse + coor)
// ---------------------------------------------------------------------------
#define GATH1 (BS*SPEMB*NHALF)   // 524288
#define GATH2 (BS*NHALF*COORD)   // 65536
__global__ void gather_kernel(const float* __restrict__ sf,
                              const float* __restrict__ coor,
                              float* __restrict__ out_sp,
                              float* __restrict__ out_co) {
    int t = blockIdx.x * blockDim.x + threadIdx.x;
    if (t < GATH1) {
        int s = t % NHALF;
        int e = (t / NHALF) % SPEMB;
        int b = t / (NHALF * SPEMB);
        out_sp[t] = sf[((size_t)b * SPEMB + e) * NSTK + g_idx[b * NHALF + s]];
    } else if (t < GATH1 + GATH2) {
        int t2 = t - GATH1;
        int c = t2 % COORD;
        int s = (t2 / COORD) % NHALF;
        int b = t2 / (COORD * NHALF);
        out_co[t2] = coor[((size_t)b * NSTK + g_idx[b * NHALF + s]) * COORD + c];
    }
}

// ---------------------------------------------------------------------------
// 4) Weight split -> A blobs [12][2][128 m][64 i] bf16 (k-reordered).
//    blob (j, mt), jc = j%6: kk = jc>>1, i0 = (jc&1)*64;
//    A[m][i] = w[(mt*128+m)*384 + (i0+i)*3 + kk]; j<6: hi, j>=6: lo.
// ---------------------------------------------------------------------------
__global__ void wsplit_kernel(const float* __restrict__ w) {
    int blk = blockIdx.x;           // 0..23 = j*2 + mt
    int j   = blk >> 1;
    int mt  = blk & 1;
    int jc  = j % 6;
    int kk  = jc >> 1;
    int i0  = (jc & 1) * 64;
    __nv_bfloat16* blob = g_Ab + (size_t)blk * (128 * 64);
    for (int e = threadIdx.x; e < 128 * 64; e += 256) {
        int m  = e >> 6;
        int il = e & 63;
        float val = w[(size_t)(mt * 128 + m) * KTOT + (i0 + il) * 3 + kk];
        __nv_bfloat16 hv = __float2bfloat16(val);
        blob[e] = (j < 6) ? hv : __float2bfloat16(val - __bfloat162float(hv));
    }
}

// ---------------------------------------------------------------------------
// 5) Fused im2col + mma.sync bf16 GEMM. CTA tile M=128 x N=64, 3 CTAs/SM.
//    smem: [0,16K) Ah, [16K,32K) Al, [32K,40K) Bh, [40K,48K) Bl.
// ---------------------------------------------------------------------------
__global__ void __launch_bounds__(256, 3) gemm_kernel(const float* __restrict__ dense,
                                                      const float* __restrict__ bias) {
    extern __shared__ char sm[];
    const uint32_t smb = smem_u32(sm);
    const int nt   = blockIdx.x;     // 0..1023
    const int mt   = blockIdx.y;     // 0..1
    const int b    = nt >> 4;
    const int sgq  = nt & 15;        // 2-stroke group
    const int tid  = threadIdx.x;
    const int wid  = tid >> 5;
    const int lane = tid & 31;
    const int mg   = wid & 3;     // m base = mg*32
    const int ng   = wid >> 2;    // n base = ng*32

    int idx2[2];
    #pragma unroll
    for (int s = 0; s < 2; s++) idx2[s] = g_idx[b * NHALF + sgq * 2 + s];

    // A loader: chunk c -> Ah +0, Al +16384 (XOR-16B swizzle)
    auto loadA = [&](int c) {
        const char* srcH = (const char*)(g_Ab + ((size_t)(c * 2 + mt)) * (128 * 64));
        const char* srcL = (const char*)(g_Ab + ((size_t)((6 + c) * 2 + mt)) * (128 * 64));
        #pragma unroll
        for (int jj = 0; jj < 4; jj++) {        // 1024 x 16B per blob
            int f = tid + jj * 256;
            int row = f >> 3, g = f & 7;
            uint32_t off = row * 128 + ((g * 16) ^ ((row & 7) * 16));
            cp16(smb + off,         srcH + f * 16);
            cp16(smb + 16384 + off, srcL + f * 16);
        }
        asm volatile("cp.async.commit_group;\n");
    };

    // B builder -> Bh +32768, Bl +40960. Thread does an (il, il+1) bf16x2 pair.
    // B[n][il] = X[b, i0+il, idx2[n>>5]*64 + 2*(n&31) + kk - 1]; left zero pad only.
    auto buildB = [&](int c) {
        int kk = c >> 1;
        int i0 = (c & 1) * 64;
        char* bH = sm + 32768;
        #pragma unroll
        for (int jj = 0; jj < 8; jj++) {
            int e   = tid + jj * 256;        // 0..2047
            int il2 = e >> 6;                // 0..31 -> il = 2*il2
            int n   = e & 63;
            int s_l = n >> 5, q = n & 31;
            int p = 2 * q + kk - 1;
            float v0 = 0.f, v1 = 0.f;
            if (p >= 0) {
                const float* xr = dense + ((size_t)(b * DNIN + i0 + 2 * il2)) * NTOTPNT
                                 + idx2[s_l] * NPNT + p;
                v0 = xr[0];
                v1 = xr[NTOTPNT];
            }
            float h0 = __bfloat162float(__float2bfloat16(v0));
            float h1 = __bfloat162float(__float2bfloat16(v1));
            uint32_t sw = n * 128 + ((il2 * 4) ^ ((n & 7) * 16));
            *(uint32_t*)(bH + sw)        = pack_bf16x2(h0, h1);
            *(uint32_t*)(bH + 8192 + sw) = pack_bf16x2(v0 - h0, v1 - h1);
        }
    };

    float acc[2][4][4];
    #pragma unroll
    for (int mi = 0; mi < 2; mi++)
        #pragma unroll
        for (int n8 = 0; n8 < 4; n8++)
            #pragma unroll
            for (int r = 0; r < 4; r++) acc[mi][n8][r] = 0.f;

    const int rowSel = lane & 15;
    const int kSel   = (lane >> 4) * 16;

    #pragma unroll 1
    for (int c = 0; c < NCHUNK; c++) {
        loadA(c);               // async; latency hidden behind buildB
        buildB(c);
        asm volatile("cp.async.wait_group 0;" ::: "memory");
        __syncthreads();

        #pragma unroll 1
        for (int pass = 0; pass < 3; pass++) {
            const uint32_t aB = smb + ((pass == 1) ? 16384u : 0u);
            const uint32_t bB = smb + 32768u + ((pass == 2) ? 8192u : 0u);
            #pragma unroll
            for (int kb = 0; kb < 4; kb++) {
                uint32_t A[2][4], Bf[2][4];
                #pragma unroll
                for (int mi = 0; mi < 2; mi++) {
                    int row = mg * 32 + mi * 16 + rowSel;
                    ldsm_x4(aB + row * 128 + ((kb * 32 + kSel) ^ ((row & 7) * 16)), A[mi]);
                }
                #pragma unroll
                for (int np = 0; np < 2; np++) {
                    int row = ng * 32 + np * 16 + rowSel;
                    ldsm_x4(bB + row * 128 + ((kb * 32 + kSel) ^ ((row & 7) * 16)), Bf[np]);
                }
                #pragma unroll
                for (int mi = 0; mi < 2; mi++)
                    #pragma unroll
                    for (int n8 = 0; n8 < 4; n8++)
                        mma16816(acc[mi][n8], A[mi],
                                 Bf[n8 >> 1][n8 & 1], Bf[n8 >> 1][(n8 & 1) + 2]);
            }
        }
        __syncthreads();    // all reads done before next chunk overwrites
    }

    // ---- epilogue: fragments -> smem Ds[128][68], then coalesced out + BN
    float* Ds = (float*)sm;
    #pragma unroll
    for (int mi = 0; mi < 2; mi++) {
        int row0 = mg * 32 + mi * 16 + (lane >> 2);
        #pragma unroll
        for (int n8 = 0; n8 < 4; n8++) {
            int col = ng * 32 + n8 * 8 + (lane & 3) * 2;
            Ds[row0 * 68 + col]           = acc[mi][n8][0];
            Ds[row0 * 68 + col + 1]       = acc[mi][n8][1];
            Ds[(row0 + 8) * 68 + col]     = acc[mi][n8][2];
            Ds[(row0 + 8) * 68 + col + 1] = acc[mi][n8][3];
        }
    }
    __syncthreads();

    // write-out: each warp covers 16 m rows, 2 rows per iter (16 lanes x float4)
    #pragma unroll 1
    for (int r2 = 0; r2 < 8; r2++) {
        int m = wid * 16 + r2 * 2 + (lane >> 4);   // 0..127
        int o = mt * 128 + m;
        float bo = __ldg(bias + o);
        float4 v = *(float4*)(Ds + m * 68 + (lane & 15) * 4);
        v.x += bo; v.y += bo; v.z += bo; v.w += bo;
        *(float4*)(g_y + ((size_t)(b * DNOUT + o)) * 1024 + sgq * 64 + (lane & 15) * 4) = v;
        float s1 = v.x + v.y + v.z + v.w;
        float s2 = v.x * v.x + v.y * v.y + v.z * v.z + v.w * v.w;
        #pragma unroll
        for (int d = 8; d > 0; d >>= 1) {          // reduce within 16-lane half
            s1 += __shfl_xor_sync(0xffffffffu, s1, d);
            s2 += __shfl_xor_sync(0xffffffffu, s2, d);
        }
        if ((lane & 15) == 0) {
            g_ps[o * NTILES + nt] = s1;
            g_pq[o * NTILES + nt] = s2;
        }
    }
}

// ---------------------------------------------------------------------------
// 6) BN stats finalize (1024 partials per channel)
// ---------------------------------------------------------------------------
__global__ void bnstat_kernel() {
    int o = blockIdx.x;
    int t = threadIdx.x;
    float s1 = 0.f, s2 = 0.f;
    for (int k = t; k < NTILES; k += 256) {
        s1 += g_ps[o * NTILES + k];
        s2 += g_pq[o * NTILES + k];
    }
    __shared__ float a[256], c[256];
    a[t] = s1; c[t] = s2;
    __syncthreads();
    for (int st = 128; st > 0; st >>= 1) {
        if (t < st) { a[t] += a[t + st]; c[t] += c[t + st]; }
        __syncthreads();
    }
    if (t == 0) {
        const float N = (float)(BS * NHALF * QOUT);
        float mean = a[0] / N;
        float var  = c[0] / N - mean * mean;
        g_mean[o] = mean;
        g_rstd[o] = rsqrtf(var + 1e-5f);
    }
}

// ---------------------------------------------------------------------------
// 7) Normalize + affine + tanh-GELU
// ---------------------------------------------------------------------------
__device__ __forceinline__ float gelu_tanh(float x) {
    float x3 = x * x * x;
    return 0.5f * x * (1.f + tanhf(0.7978845608028654f * (x + 0.044715f * x3)));
}
__global__ void norm_kernel(const float* __restrict__ gamma,
                            const float* __restrict__ beta,
                            float* __restrict__ out)
{
    const int TOT4 = YTOT / 4;
    int t = blockIdx.x * blockDim.x + threadIdx.x;
    if (t >= TOT4) return;
    int o = (t >> 8) & (DNOUT - 1);
    float r  = g_rstd[o];
    float m  = g_mean[o];
    float g  = gamma[o] * r;
    float bb = beta[o] - m * g;
    float4 v = ((const float4*)g_y)[t];
    float4 w;
    w.x = gelu_tanh(v.x * g + bb);
    w.y = gelu_tanh(v.y * g + bb);
    w.z = gelu_tanh(v.z * g + bb);
    w.w = gelu_tanh(v.w * g + bb);
    ((float4*)out)[t] = w;
}

// ---------------------------------------------------------------------------
// Launch
// ---------------------------------------------------------------------------
extern "C" void kernel_launch(void* const* d_in, const int* in_sizes, int n_in,
                              void* d_out, int out_size)
{
    const float* sparse_fea = (const float*)d_in[0];  // [64,256,64]
    const float* dense_fea  = (const float*)d_in[1];  // [64,128,4096]
    const float* stk_coor   = (const float*)d_in[2];  // [64,64,32]
    const float* conv_w     = (const float*)d_in[3];  // [256,128,1,3]
    const float* conv_b     = (const float*)d_in[4];  // [256]
    const float* bn_gamma   = (const float*)d_in[5];  // [256]
    const float* bn_beta    = (const float*)d_in[6];  // [256]

    float* out_sparse = (float*)d_out;
    float* out_dense  = out_sparse + BS * SPEMB * NHALF;
    float* out_coor   = out_dense + YTOT;

    cudaFuncSetAttribute(gemm_kernel,
                         cudaFuncAttributeMaxDynamicSharedMemorySize, SMEM_GEMM);

    fps_kernel<<<BS, NSTK>>>(stk_coor);
    wsplit_kernel<<<24, 256>>>(conv_w);

    gather_kernel<<<(GATH1 + GATH2 + 255) / 256, 256>>>(sparse_fea, stk_coor,
                                                        out_sparse, out_coor);

    dim3 ggrid(NTILES, 2);
    gemm_kernel<<<ggrid, 256, SMEM_GEMM>>>(dense_fea, conv_b);

    bnstat_kernel<<<DNOUT, 256>>>();
    norm_kernel<<<(YTOT / 4 + 255) / 256, 256>>>(bn_gamma, bn_beta, out_dense);
}